// round 4
// baseline (speedup 1.0000x reference)
#include <cuda_runtime.h>
#include <math.h>

#define NN     50000
#define RR     4
#define DD     5
#define BB     8
#define TT     10
#define E_RECN 1500000
#define E_INN  200000
#define N_INN  17400
#define RNN    (RR * NN)   // 200000
#define ZLEN   (DD * NN)   // 250000

#define REC_QUADS (E_RECN / 4)             // 375000
#define IN_QUADS  (E_INN / 4)              // 50000
#define ALL_QUADS (REC_QUADS + IN_QUADS)   // 425000

#define SCAN_CH   1024
#define SCAN_NBLK ((ZLEN + SCAN_CH - 1) / SCAN_CH)   // 245  (<=256)

// ------------------------- device scratch (no allocs) -------------------------
__device__ float4        g_total[BB * NN];
__device__ float         g_v[BB * NN];
__device__ float         g_r[BB * NN];
__device__ float         g_a1[BB * NN];
__device__ float         g_a2[BB * NN];
__device__ float4        g_psc_rise[BB * NN];
__device__ float4        g_psc[BB * NN];
__device__ unsigned char g_zmask[ZLEN];
__device__ unsigned char g_xmask[TT * N_INN];
__device__ float2        g_ascd[NN];

// sort scratch / sorted edge arrays
__device__ int  g_zidx[E_RECN];       // per original edge: d*NN + n
__device__ int  g_cnt[ZLEN];
__device__ int  g_part[256];
__device__ int  g_fill[ZLEN];
__device__ int  g_srt_zidx[E_RECN];   // sorted by zidx
__device__ int2 g_srt_edge[E_RECN];   // (tgt, w) sorted by zidx

// ------------------------------- init kernel ---------------------------------
__global__ void init_kernel(const float* __restrict__ x,
                            const float* __restrict__ bkg_w,
                            const float2* __restrict__ param_k,
                            const float* __restrict__ v0)
{
    int i      = blockIdx.x * blockDim.x + threadIdx.x;
    int stride = gridDim.x * blockDim.x;

    const float4* bkg4 = reinterpret_cast<const float4*>(bkg_w);
    for (int j = i; j < BB * NN; j += stride) {
        g_total[j] = bkg4[j % NN];
        g_v[j]  = v0[j];
        g_r[j]  = 0.0f;
        g_a1[j] = 0.0f;
        g_a2[j] = 0.0f;
        g_psc_rise[j] = make_float4(0.f, 0.f, 0.f, 0.f);
        g_psc[j]      = make_float4(0.f, 0.f, 0.f, 0.f);
    }
    for (int j = i; j < ZLEN; j += stride) { g_zmask[j] = 0; g_cnt[j] = 0; }
    for (int j = i; j < TT * N_INN; j += stride) {
        int t = j / N_INN;
        int s = j - t * N_INN;
        unsigned m = 0;
        #pragma unroll
        for (int b = 0; b < BB; b++) {
            if (x[(t * BB + b) * N_INN + s] > 0.5f) m |= (1u << b);
        }
        g_xmask[j] = (unsigned char)m;
    }
    for (int j = i; j < NN; j += stride) {
        float2 pk = param_k[j];
        float s0 = 1.0f / (1.0f + expf(-pk.x));
        float s1 = 1.0f / (1.0f + expf(-pk.y));
        g_ascd[j] = make_float2(expf(-s0), expf(-s1));
    }
}

// ------------------------- edge sort by source zidx ---------------------------
__global__ void hist_kernel(const int* __restrict__ rec_src)
{
    int i      = blockIdx.x * blockDim.x + threadIdx.x;
    int stride = gridDim.x * blockDim.x;
    for (int e = i; e < E_RECN; e += stride) {
        int src = rec_src[e];
        int d = src / NN;
        int n = src - d * NN;
        int j = d * NN + n;
        g_zidx[e] = j;
        atomicAdd(&g_cnt[j], 1);
    }
}

__global__ void scan1_kernel()   // sums of 1024-wide chunks
{
    __shared__ int sh[256];
    int bid = blockIdx.x, tid = threadIdx.x;
    int base = bid * SCAN_CH + tid * 4;
    int s = 0;
    #pragma unroll
    for (int k = 0; k < 4; k++) {
        int idx = base + k;
        if (idx < ZLEN) s += g_cnt[idx];
    }
    sh[tid] = s; __syncthreads();
    for (int off = 128; off > 0; off >>= 1) {
        if (tid < off) sh[tid] += sh[tid + off];
        __syncthreads();
    }
    if (tid == 0) g_part[bid] = sh[0];
}

__global__ void scan2_kernel()   // parallel exclusive scan of 245 partials
{
    __shared__ int sh[256];
    int tid = threadIdx.x;
    int v = (tid < SCAN_NBLK) ? g_part[tid] : 0;
    sh[tid] = v; __syncthreads();
    for (int off = 1; off < 256; off <<= 1) {
        int u = (tid >= off) ? sh[tid - off] : 0;
        __syncthreads();
        sh[tid] += u;
        __syncthreads();
    }
    if (tid < SCAN_NBLK) g_part[tid] = sh[tid] - v;
}

__global__ void scan3_kernel()   // per-chunk exclusive scan -> fill cursors
{
    __shared__ int sh[256];
    int bid = blockIdx.x, tid = threadIdx.x;
    int base = bid * SCAN_CH + tid * 4;
    int c[4], local[4];
    #pragma unroll
    for (int k = 0; k < 4; k++) {
        int idx = base + k;
        c[k] = (idx < ZLEN) ? g_cnt[idx] : 0;
    }
    int s = 0;
    #pragma unroll
    for (int k = 0; k < 4; k++) { local[k] = s; s += c[k]; }
    sh[tid] = s; __syncthreads();
    for (int off = 1; off < 256; off <<= 1) {
        int v = (tid >= off) ? sh[tid - off] : 0;
        __syncthreads();
        sh[tid] += v;
        __syncthreads();
    }
    int tpre = sh[tid] - s;
    int bbase = g_part[bid];
    #pragma unroll
    for (int k = 0; k < 4; k++) {
        int idx = base + k;
        if (idx < ZLEN) g_fill[idx] = bbase + tpre + local[k];
    }
}

__global__ void sort_kernel(const int* __restrict__ rec_tgt,
                            const float* __restrict__ w_rec)
{
    int i      = blockIdx.x * blockDim.x + threadIdx.x;
    int stride = gridDim.x * blockDim.x;
    for (int e = i; e < E_RECN; e += stride) {
        int j = g_zidx[e];
        int pos = atomicAdd(&g_fill[j], 1);
        g_srt_zidx[e < 0 ? 0 : pos] = j;     // (guard is no-op; keeps compiler honest)
        g_srt_edge[pos] = make_int2(rec_tgt[e], __float_as_int(w_rec[e]));
    }
}

// ------------------------------ scatter kernel -------------------------------
// Edge-parallel over SORTED recurrent edges: warp's zmask gathers are coalesced
// (adjacent zidx), early-out is warp-coherent. Input edges: quad-per-thread.
__global__ __launch_bounds__(256)
void scatter_kernel(const int*   __restrict__ in_src,
                    const int*   __restrict__ in_tgt,
                    const float* __restrict__ w_in,
                    int h_read, int t)
{
    int q = blockIdx.x * blockDim.x + threadIdx.x;
    float* tot = reinterpret_cast<float*>(g_total);
    const int base = h_read * NN;

    if (q < REC_QUADS) {
        const int e0 = q * 4;
        int4 zi = *reinterpret_cast<const int4*>(&g_srt_zidx[e0]);

        int i0 = zi.x + base; if (i0 >= ZLEN) i0 -= ZLEN;
        int i1 = zi.y + base; if (i1 >= ZLEN) i1 -= ZLEN;
        int i2 = zi.z + base; if (i2 >= ZLEN) i2 -= ZLEN;
        int i3 = zi.w + base; if (i3 >= ZLEN) i3 -= ZLEN;

        unsigned m0 = g_zmask[i0];
        unsigned m1 = g_zmask[i1];
        unsigned m2 = g_zmask[i2];
        unsigned m3 = g_zmask[i3];

        if ((m0 | m1 | m2 | m3) == 0u) return;

        int4 p0 = *reinterpret_cast<const int4*>(&g_srt_edge[e0]);     // edges e0,e0+1
        int4 p1 = *reinterpret_cast<const int4*>(&g_srt_edge[e0 + 2]); // edges e0+2,e0+3

        unsigned ms[4]  = {m0, m1, m2, m3};
        int      tgs[4] = {p0.x, p0.z, p1.x, p1.z};
        float    wws[4] = {__int_as_float(p0.y), __int_as_float(p0.w),
                           __int_as_float(p1.y), __int_as_float(p1.w)};
        #pragma unroll
        for (int k = 0; k < 4; k++) {
            unsigned m = ms[k];
            if (!m) continue;
            float w = wws[k];
            int tgt = tgs[k];
            #pragma unroll
            for (int b = 0; b < BB; b++) {
                if (m & (1u << b)) atomicAdd(&tot[b * RNN + tgt], w);
            }
        }
    } else if (q < ALL_QUADS) {
        const int e0 = (q - REC_QUADS) * 4;
        int4 si = *reinterpret_cast<const int4*>(&in_src[e0]);
        const unsigned char* xm = &g_xmask[t * N_INN];

        unsigned m0 = xm[si.x], m1 = xm[si.y], m2 = xm[si.z], m3 = xm[si.w];
        if ((m0 | m1 | m2 | m3) == 0u) return;

        int4   tg = *reinterpret_cast<const int4*>  (&in_tgt[e0]);
        float4 ww = *reinterpret_cast<const float4*>(&w_in[e0]);
        unsigned ms[4]  = {m0, m1, m2, m3};
        int      tgs[4] = {tg.x, tg.y, tg.z, tg.w};
        float    wws[4] = {ww.x, ww.y, ww.z, ww.w};
        #pragma unroll
        for (int k = 0; k < 4; k++) {
            unsigned m = ms[k];
            if (!m) continue;
            float w = wws[k];
            int tgt = tgs[k];
            #pragma unroll
            for (int b = 0; b < BB; b++) {
                if (m & (1u << b)) atomicAdd(&tot[b * RNN + tgt], w);
            }
        }
    }
}

// ------------------------------ update kernel --------------------------------
__global__ __launch_bounds__(256)
void update_kernel(const float*  __restrict__ decay,
                   const float*  __restrict__ current_factor,
                   const float*  __restrict__ v_th,
                   const float*  __restrict__ e_l,
                   const float*  __restrict__ v_reset,
                   const float*  __restrict__ t_ref,
                   const float2* __restrict__ asc_amps,
                   const float*  __restrict__ param_g,
                   const float4* __restrict__ syn_decay,
                   const float4* __restrict__ psc_initial,
                   const float4* __restrict__ bkg4,
                   float*        __restrict__ out,
                   int h_read, int h_write, int t)
{
    int n = blockIdx.x * blockDim.x + threadIdx.x;
    if (n >= NN) return;

    const float  dec  = decay[n];
    const float  cf   = current_factor[n];
    const float  vth  = v_th[n];
    const float  el   = e_l[n];
    const float  vre  = v_reset[n];
    const float  tref = t_ref[n];
    const float2 amps = asc_amps[n];
    const float2 ad   = g_ascd[n];
    const float  g    = param_g[n];
    const float4 sd   = syn_decay[n];
    const float4 pi   = psc_initial[n];
    const float4 bk   = bkg4[n];

    const float gel    = g * el;
    const float invden = 1.0f / (vth - el);
    const float rstamp = vre - vth;

    unsigned pm = g_zmask[h_read * NN + n];
    unsigned nm = 0;

    #pragma unroll
    for (int b = 0; b < BB; b++) {
        int bn = b * NN + n;
        float4 total = g_total[bn];
        float4 pr = g_psc_rise[bn];
        float4 pc = g_psc[bn];
        float  v  = g_v[bn];
        float  r  = g_r[bn];
        float  a1 = g_a1[bn];
        float  a2 = g_a2[bn];
        float  pz = (pm >> b) & 1u ? 1.0f : 0.0f;

        float input_cur = pc.x + pc.y + pc.z + pc.w;
        float c1   = input_cur + a1 + a2 + gel;
        float newv = dec * v + cf * c1 + pz * rstamp;
        float newr = fmaxf(r + pz * tref - 1.0f, 0.0f);
        float na1  = ad.x * a1 + pz * amps.x;
        float na2  = ad.y * a2 + pz * amps.y;

        float4 npc, npr;
        npc.x = pc.x * sd.x + sd.x * pr.x;
        npc.y = pc.y * sd.y + sd.y * pr.y;
        npc.z = pc.z * sd.z + sd.z * pr.z;
        npc.w = pc.w * sd.w + sd.w * pr.w;
        npr.x = sd.x * pr.x + pi.x * total.x;
        npr.y = sd.y * pr.y + pi.y * total.y;
        npr.z = sd.z * pr.z + pi.z * total.z;
        npr.w = sd.w * pr.w + pi.w * total.w;

        float vsc = (newv - vth) * invden;
        float z = (vsc > 0.0f) ? 1.0f : 0.0f;
        if (newr > 0.0f) z = 0.0f;
        nm |= (z != 0.0f ? 1u : 0u) << b;

        g_v[bn]  = newv;
        g_r[bn]  = newr;
        g_a1[bn] = na1;
        g_a2[bn] = na2;
        g_psc_rise[bn] = npr;
        g_psc[bn]      = npc;
        g_total[bn] = bk;

        out[(t * BB + b) * NN + n] = z;
    }
    g_zmask[h_write * NN + n] = (unsigned char)nm;
}

// --------------------------------- launcher ----------------------------------
extern "C" void kernel_launch(void* const* d_in, const int* in_sizes, int n_in,
                              void* d_out, int out_size)
{
    const float* x        = (const float*)d_in[0];
    const float* w_rec    = (const float*)d_in[1];
    const int*   rec_src  = (const int*)  d_in[2];
    const int*   rec_tgt  = (const int*)  d_in[3];
    const float* w_in     = (const float*)d_in[4];
    const int*   in_src   = (const int*)  d_in[5];
    const int*   in_tgt   = (const int*)  d_in[6];
    const float* bkg_w    = (const float*)d_in[7];
    const float* decay    = (const float*)d_in[8];
    const float* cf       = (const float*)d_in[9];
    const float* v_th     = (const float*)d_in[10];
    const float* e_l      = (const float*)d_in[11];
    const float* v_reset  = (const float*)d_in[12];
    const float* t_ref    = (const float*)d_in[13];
    const float2* asc_amps = (const float2*)d_in[14];
    const float2* param_k  = (const float2*)d_in[15];
    const float* param_g   = (const float*)d_in[16];
    const float4* syn_decay   = (const float4*)d_in[17];
    const float4* psc_initial = (const float4*)d_in[18];
    const float* v0        = (const float*)d_in[19];
    float* out = (float*)d_out;

    init_kernel<<<1024, 256>>>(x, bkg_w, param_k, v0);

    hist_kernel<<<1024, 256>>>(rec_src);
    scan1_kernel<<<SCAN_NBLK, 256>>>();
    scan2_kernel<<<1, 256>>>();
    scan3_kernel<<<SCAN_NBLK, 256>>>();
    sort_kernel<<<1024, 256>>>(rec_tgt, w_rec);

    const int scatter_blocks = (ALL_QUADS + 255) / 256;
    const int update_blocks  = (NN + 255) / 256;

    int h = 0;
    for (int t = 0; t < TT; t++) {
        int h_read  = h;
        int h_write = (h + DD - 1) % DD;
        scatter_kernel<<<scatter_blocks, 256>>>(in_src, in_tgt, w_in, h_read, t);
        update_kernel<<<update_blocks, 256>>>(decay, cf, v_th, e_l, v_reset, t_ref,
                                              asc_amps, param_g, syn_decay, psc_initial,
                                              (const float4*)bkg_w, out,
                                              h_read, h_write, t);
        h = h_write;
    }
}

// round 5
// speedup vs baseline: 1.5167x; 1.5167x over previous
#include <cuda_runtime.h>
#include <math.h>

#define NN     50000
#define RR     4
#define DD     5
#define BB     8
#define TT     10
#define E_RECN 1500000
#define E_INN  200000
#define N_INN  17400
#define RNN    (RR * NN)   // 200000
#define ZLEN   (DD * NN)   // 250000
#define IN_QUADS (E_INN / 4)   // 50000

#define U_BLKS   196           // ceil(50000/256)
#define SE_BLKS  1280
#define F_GRID   (U_BLKS + SE_BLKS)

#define D0_CAP   400000        // capacity for d=0 edges (expected ~300K)

// scan config for 50K-bin exclusive scan (d0 CSR rowptr)
#define SC_CH    1024
#define SC_NBLK  ((NN + SC_CH - 1) / SC_CH)   // 49

// ------------------------- device scratch (no allocs) -------------------------
__device__ float4        g_totA[BB * NN];
__device__ float4        g_totB[BB * NN];
__device__ float         g_v[BB * NN];
__device__ float         g_r[BB * NN];
__device__ float         g_a1[BB * NN];
__device__ float         g_a2[BB * NN];
__device__ float4        g_psc_rise[BB * NN];
__device__ float4        g_psc[BB * NN];
__device__ unsigned char g_zmask[ZLEN];
__device__ unsigned char g_xmask[TT * N_INN];
__device__ float2        g_ascd[NN];

// delay-partitioned edge lists (d = 1..4), padded to multiple-of-4 per list
__device__ int   g_e_n  [E_RECN + 16];
__device__ int   g_e_tgt[E_RECN + 16];
__device__ float g_e_w  [E_RECN + 16];
__device__ int   g_doffA[5];    // [0..3] = start of list d=1..4, [4] = padded total
__device__ int   g_dfill[4];    // append cursors
__device__ int   g_dcnt[5];     // raw counts per delay

// d=0 edges: CSR by source neuron
__device__ int   g_cnt0[NN];
__device__ int   g_part0[64];
__device__ int   g_rowptr0[NN + 1];
__device__ int   g_fill0[NN];
__device__ int2  g_d0_edge[D0_CAP];

// per-source-step spike activity flags: g_any[5 + s] for step s (s in [-5, TT))
__device__ int   g_any[16];

// ------------------------------- init kernel ---------------------------------
__global__ void init_kernel(const float* __restrict__ x,
                            const float* __restrict__ bkg_w,
                            const float2* __restrict__ param_k,
                            const float* __restrict__ v0)
{
    int i      = blockIdx.x * blockDim.x + threadIdx.x;
    int stride = gridDim.x * blockDim.x;

    if (i < 16) g_any[i] = 0;
    if (i < 5)  g_dcnt[i] = 0;

    const float4* bkg4 = reinterpret_cast<const float4*>(bkg_w);
    for (int j = i; j < BB * NN; j += stride) {
        float4 bk = bkg4[j % NN];
        g_totA[j] = bk;
        g_totB[j] = bk;
        g_v[j]  = v0[j];
        g_r[j]  = 0.0f;
        g_a1[j] = 0.0f;
        g_a2[j] = 0.0f;
        g_psc_rise[j] = make_float4(0.f, 0.f, 0.f, 0.f);
        g_psc[j]      = make_float4(0.f, 0.f, 0.f, 0.f);
    }
    for (int j = i; j < ZLEN; j += stride) g_zmask[j] = 0;
    for (int j = i; j < NN; j += stride) g_cnt0[j] = 0;
    for (int j = i; j < TT * N_INN; j += stride) {
        int t = j / N_INN;
        int s = j - t * N_INN;
        unsigned m = 0;
        #pragma unroll
        for (int b = 0; b < BB; b++) {
            if (x[(t * BB + b) * N_INN + s] > 0.5f) m |= (1u << b);
        }
        g_xmask[j] = (unsigned char)m;
    }
    for (int j = i; j < NN; j += stride) {
        float2 pk = param_k[j];
        float s0 = 1.0f / (1.0f + expf(-pk.x));
        float s1 = 1.0f / (1.0f + expf(-pk.y));
        g_ascd[j] = make_float2(expf(-s0), expf(-s1));
    }
}

// ---------------------- prep pass A: histograms --------------------------------
__global__ void histA_kernel(const int* __restrict__ rec_src)
{
    __shared__ int sd[5];
    if (threadIdx.x < 5) sd[threadIdx.x] = 0;
    __syncthreads();
    int i = blockIdx.x * blockDim.x + threadIdx.x;
    int stride = gridDim.x * blockDim.x;
    for (int e = i; e < E_RECN; e += stride) {
        int src = rec_src[e];
        int d = src / NN;
        int n = src - d * NN;
        if (d == 0) atomicAdd(&g_cnt0[n], 1);
        atomicAdd(&sd[d], 1);
    }
    __syncthreads();
    if (threadIdx.x >= 1 && threadIdx.x < 5)
        atomicAdd(&g_dcnt[threadIdx.x], sd[threadIdx.x]);
}

// ---------------------- prep scans for d0 CSR ----------------------------------
__global__ void scanA_kernel()   // partial sums of 1024-chunks of g_cnt0
{
    __shared__ int sh[256];
    int bid = blockIdx.x, tid = threadIdx.x;
    int base = bid * SC_CH + tid * 4;
    int s = 0;
    #pragma unroll
    for (int k = 0; k < 4; k++) {
        int idx = base + k;
        if (idx < NN) s += g_cnt0[idx];
    }
    sh[tid] = s; __syncthreads();
    for (int off = 128; off > 0; off >>= 1) {
        if (tid < off) sh[tid] += sh[tid + off];
        __syncthreads();
    }
    if (tid == 0) g_part0[bid] = sh[0];
}

__global__ void scanB_kernel()   // scan partials + delay-list offsets + pads
{
    __shared__ int sh[64];
    int tid = threadIdx.x;
    int v = (tid < SC_NBLK) ? g_part0[tid] : 0;
    sh[tid] = v; __syncthreads();
    for (int off = 1; off < 64; off <<= 1) {
        int u = (tid >= off) ? sh[tid - off] : 0;
        __syncthreads();
        sh[tid] += u;
        __syncthreads();
    }
    if (tid < SC_NBLK) g_part0[tid] = sh[tid] - v;
    if (tid == 0) {
        g_rowptr0[NN] = sh[63];   // total d0 edges
        int off = 0;
        for (int d = 1; d <= 4; d++) {
            g_doffA[d - 1] = off;
            g_dfill[d - 1] = off;
            int c  = g_dcnt[d];
            int ru = (c + 3) & ~3;
            for (int p = c; p < ru; p++) {   // benign pad entries (w=0)
                g_e_n[off + p]   = 0;
                g_e_tgt[off + p] = 0;
                g_e_w[off + p]   = 0.0f;
            }
            off += ru;
        }
        g_doffA[4] = off;
    }
}

__global__ void scanC_kernel()   // per-chunk exclusive scan -> rowptr0, fill0
{
    __shared__ int sh[256];
    int bid = blockIdx.x, tid = threadIdx.x;
    int base = bid * SC_CH + tid * 4;
    int c[4], local[4];
    #pragma unroll
    for (int k = 0; k < 4; k++) {
        int idx = base + k;
        c[k] = (idx < NN) ? g_cnt0[idx] : 0;
    }
    int s = 0;
    #pragma unroll
    for (int k = 0; k < 4; k++) { local[k] = s; s += c[k]; }
    sh[tid] = s; __syncthreads();
    for (int off = 1; off < 256; off <<= 1) {
        int v = (tid >= off) ? sh[tid - off] : 0;
        __syncthreads();
        sh[tid] += v;
        __syncthreads();
    }
    int tpre = sh[tid] - s;
    int bbase = g_part0[bid];
    #pragma unroll
    for (int k = 0; k < 4; k++) {
        int idx = base + k;
        if (idx < NN) {
            int val = bbase + tpre + local[k];
            g_rowptr0[idx] = val;
            g_fill0[idx]   = val;
        }
    }
}

// ---------------------- prep pass C: partition edges ---------------------------
__global__ __launch_bounds__(256)
void partition_kernel(const int* __restrict__ rec_src,
                      const int* __restrict__ rec_tgt,
                      const float* __restrict__ w_rec)
{
    __shared__ int scnt[4], sbase[4];
    if (threadIdx.x < 4) scnt[threadIdx.x] = 0;
    __syncthreads();

    int e = blockIdx.x * blockDim.x + threadIdx.x;
    int d = 0, n = 0, tgt = 0, ticket = -1;
    float w = 0.0f;
    if (e < E_RECN) {
        int src = rec_src[e];
        d = src / NN;
        n = src - d * NN;
        tgt = rec_tgt[e];
        w   = w_rec[e];
        if (d == 0) {
            int pos = atomicAdd(&g_fill0[n], 1);
            g_d0_edge[pos] = make_int2(tgt, __float_as_int(w));
        } else {
            ticket = atomicAdd(&scnt[d - 1], 1);
        }
    }
    __syncthreads();
    if (threadIdx.x < 4 && scnt[threadIdx.x] > 0)
        sbase[threadIdx.x] = atomicAdd(&g_dfill[threadIdx.x], scnt[threadIdx.x]);
    __syncthreads();
    if (ticket >= 0) {
        int pos = sbase[d - 1] + ticket;
        g_e_n[pos]   = n;
        g_e_tgt[pos] = tgt;
        g_e_w[pos]   = w;
    }
}

// ---------------------- step-0 input scatter ------------------------------------
__global__ __launch_bounds__(256)
void s0_kernel(const int* __restrict__ in_src,
               const int* __restrict__ in_tgt,
               const float* __restrict__ w_in)
{
    int q = blockIdx.x * blockDim.x + threadIdx.x;
    if (q >= IN_QUADS) return;
    float* tot = reinterpret_cast<float*>(g_totA);
    const int e0 = q * 4;
    int4 si = *reinterpret_cast<const int4*>(&in_src[e0]);
    const unsigned char* xm = &g_xmask[0];
    unsigned m0 = xm[si.x], m1 = xm[si.y], m2 = xm[si.z], m3 = xm[si.w];
    if ((m0 | m1 | m2 | m3) == 0u) return;
    int4   tg = *reinterpret_cast<const int4*>  (&in_tgt[e0]);
    float4 ww = *reinterpret_cast<const float4*>(&w_in[e0]);
    unsigned ms[4]  = {m0, m1, m2, m3};
    int      tgs[4] = {tg.x, tg.y, tg.z, tg.w};
    float    wws[4] = {ww.x, ww.y, ww.z, ww.w};
    #pragma unroll
    for (int k = 0; k < 4; k++) {
        unsigned m = ms[k];
        if (!m) continue;
        #pragma unroll
        for (int b = 0; b < BB; b++) {
            if (m & (1u << b)) atomicAdd(&tot[b * RNN + tgs[k]], wws[k]);
        }
    }
}

// ------------------------------ fused step kernel -------------------------------
// Blocks [0, U_BLKS): update step t (reads tot(t), re-inits it, scatters its own
//   d=0 fan-out into tot(t+1), writes zmask + activity flag + output spikes).
// Blocks [U_BLKS, F_GRID): scatter for step t+1 into tot(t+1): delay d>=1 edge
//   lists (skipped per-list when source step had no spikes) + input edges.
__global__ __launch_bounds__(256)
void fused_kernel(const float*  __restrict__ decay,
                  const float*  __restrict__ current_factor,
                  const float*  __restrict__ v_th,
                  const float*  __restrict__ e_l,
                  const float*  __restrict__ v_reset,
                  const float*  __restrict__ t_ref,
                  const float2* __restrict__ asc_amps,
                  const float*  __restrict__ param_g,
                  const float4* __restrict__ syn_decay,
                  const float4* __restrict__ psc_initial,
                  const float4* __restrict__ bkg4,
                  const int*    __restrict__ in_src,
                  const int*    __restrict__ in_tgt,
                  const float*  __restrict__ w_in,
                  float*        __restrict__ out,
                  int t, int h_read, int h_write)
{
    float4* totcur = (t & 1) ? g_totB : g_totA;
    float4* totnxt = (t & 1) ? g_totA : g_totB;

    if (blockIdx.x < U_BLKS) {
        // ------------------------- update role -------------------------------
        int n = blockIdx.x * blockDim.x + threadIdx.x;
        if (n >= NN) return;

        const float  dec  = decay[n];
        const float  cf   = current_factor[n];
        const float  vth  = v_th[n];
        const float  el   = e_l[n];
        const float  vre  = v_reset[n];
        const float  tref = t_ref[n];
        const float2 amps = asc_amps[n];
        const float2 ad   = g_ascd[n];
        const float  g    = param_g[n];
        const float4 sd   = syn_decay[n];
        const float4 pi   = psc_initial[n];
        const float4 bk   = bkg4[n];

        const float gel    = g * el;
        const float invden = 1.0f / (vth - el);
        const float rstamp = vre - vth;

        unsigned pm = g_zmask[h_read * NN + n];
        unsigned nm = 0;

        #pragma unroll
        for (int b = 0; b < BB; b++) {
            int bn = b * NN + n;
            float4 total = totcur[bn];
            float4 pr = g_psc_rise[bn];
            float4 pc = g_psc[bn];
            float  v  = g_v[bn];
            float  r  = g_r[bn];
            float  a1 = g_a1[bn];
            float  a2 = g_a2[bn];
            float  pz = (pm >> b) & 1u ? 1.0f : 0.0f;

            float input_cur = pc.x + pc.y + pc.z + pc.w;
            float c1   = input_cur + a1 + a2 + gel;
            float newv = dec * v + cf * c1 + pz * rstamp;
            float newr = fmaxf(r + pz * tref - 1.0f, 0.0f);
            float na1  = ad.x * a1 + pz * amps.x;
            float na2  = ad.y * a2 + pz * amps.y;

            float4 npc, npr;
            npc.x = pc.x * sd.x + sd.x * pr.x;
            npc.y = pc.y * sd.y + sd.y * pr.y;
            npc.z = pc.z * sd.z + sd.z * pr.z;
            npc.w = pc.w * sd.w + sd.w * pr.w;
            npr.x = sd.x * pr.x + pi.x * total.x;
            npr.y = sd.y * pr.y + pi.y * total.y;
            npr.z = sd.z * pr.z + pi.z * total.z;
            npr.w = sd.w * pr.w + pi.w * total.w;

            float vsc = (newv - vth) * invden;
            float z = (vsc > 0.0f) ? 1.0f : 0.0f;
            if (newr > 0.0f) z = 0.0f;
            nm |= (z != 0.0f ? 1u : 0u) << b;

            g_v[bn]  = newv;
            g_r[bn]  = newr;
            g_a1[bn] = na1;
            g_a2[bn] = na2;
            g_psc_rise[bn] = npr;
            g_psc[bn]      = npc;
            totcur[bn] = bk;                 // re-init for step t+2

            out[(t * BB + b) * NN + n] = z;
        }
        g_zmask[h_write * NN + n] = (unsigned char)nm;

        if (nm) {
            g_any[5 + t] = 1;                // benign race (all write 1)
            if (t + 1 < TT) {
                // scatter my own d=0 fan-out into next step's totals
                float* totn = reinterpret_cast<float*>(totnxt);
                int r0 = g_rowptr0[n];
                int r1 = g_rowptr0[n + 1];
                for (int e = r0; e < r1; e++) {
                    int2 tw = g_d0_edge[e];
                    float w = __int_as_float(tw.y);
                    #pragma unroll
                    for (int b = 0; b < BB; b++) {
                        if (nm & (1u << b)) atomicAdd(&totn[b * RNN + tw.x], w);
                    }
                }
            }
        }
    } else {
        // --------------------- scatter role (step t+1) -----------------------
        if (t + 1 >= TT) return;
        const int tau = t + 1;
        float* totn = reinterpret_cast<float*>(totnxt);

        const int doff2 = g_doffA[1];
        const int doff3 = g_doffA[2];
        const int doff4 = g_doffA[3];
        const int dtot  = g_doffA[4];
        const int nq1   = dtot >> 2;
        const int totq  = nq1 + IN_QUADS;

        int idx    = (blockIdx.x - U_BLKS) * blockDim.x + threadIdx.x;
        int stride = (gridDim.x - U_BLKS) * blockDim.x;

        for (int q = idx; q < totq; q += stride) {
            if (q < nq1) {
                const int e0 = q << 2;
                int d = 1 + (e0 >= doff2) + (e0 >= doff3) + (e0 >= doff4);
                if (g_any[5 + t - d] == 0) continue;   // source step had no spikes
                int slot = h_write + d; if (slot >= DD) slot -= DD;
                const unsigned char* zm = &g_zmask[slot * NN];

                int4 nn = *reinterpret_cast<const int4*>(&g_e_n[e0]);
                unsigned m0 = zm[nn.x], m1 = zm[nn.y], m2 = zm[nn.z], m3 = zm[nn.w];
                if ((m0 | m1 | m2 | m3) == 0u) continue;

                int4   tg = *reinterpret_cast<const int4*>  (&g_e_tgt[e0]);
                float4 ww = *reinterpret_cast<const float4*>(&g_e_w[e0]);
                unsigned ms[4]  = {m0, m1, m2, m3};
                int      tgs[4] = {tg.x, tg.y, tg.z, tg.w};
                float    wws[4] = {ww.x, ww.y, ww.z, ww.w};
                #pragma unroll
                for (int k = 0; k < 4; k++) {
                    unsigned m = ms[k];
                    if (!m) continue;
                    #pragma unroll
                    for (int b = 0; b < BB; b++) {
                        if (m & (1u << b)) atomicAdd(&totn[b * RNN + tgs[k]], wws[k]);
                    }
                }
            } else {
                const int e0 = (q - nq1) * 4;
                int4 si = *reinterpret_cast<const int4*>(&in_src[e0]);
                const unsigned char* xm = &g_xmask[tau * N_INN];
                unsigned m0 = xm[si.x], m1 = xm[si.y], m2 = xm[si.z], m3 = xm[si.w];
                if ((m0 | m1 | m2 | m3) == 0u) continue;

                int4   tg = *reinterpret_cast<const int4*>  (&in_tgt[e0]);
                float4 ww = *reinterpret_cast<const float4*>(&w_in[e0]);
                unsigned ms[4]  = {m0, m1, m2, m3};
                int      tgs[4] = {tg.x, tg.y, tg.z, tg.w};
                float    wws[4] = {ww.x, ww.y, ww.z, ww.w};
                #pragma unroll
                for (int k = 0; k < 4; k++) {
                    unsigned m = ms[k];
                    if (!m) continue;
                    #pragma unroll
                    for (int b = 0; b < BB; b++) {
                        if (m & (1u << b)) atomicAdd(&totn[b * RNN + tgs[k]], wws[k]);
                    }
                }
            }
        }
    }
}

// --------------------------------- launcher ----------------------------------
extern "C" void kernel_launch(void* const* d_in, const int* in_sizes, int n_in,
                              void* d_out, int out_size)
{
    const float* x        = (const float*)d_in[0];
    const float* w_rec    = (const float*)d_in[1];
    const int*   rec_src  = (const int*)  d_in[2];
    const int*   rec_tgt  = (const int*)  d_in[3];
    const float* w_in     = (const float*)d_in[4];
    const int*   in_src   = (const int*)  d_in[5];
    const int*   in_tgt   = (const int*)  d_in[6];
    const float* bkg_w    = (const float*)d_in[7];
    const float* decay    = (const float*)d_in[8];
    const float* cf       = (const float*)d_in[9];
    const float* v_th     = (const float*)d_in[10];
    const float* e_l      = (const float*)d_in[11];
    const float* v_reset  = (const float*)d_in[12];
    const float* t_ref    = (const float*)d_in[13];
    const float2* asc_amps = (const float2*)d_in[14];
    const float2* param_k  = (const float2*)d_in[15];
    const float* param_g   = (const float*)d_in[16];
    const float4* syn_decay   = (const float4*)d_in[17];
    const float4* psc_initial = (const float4*)d_in[18];
    const float* v0        = (const float*)d_in[19];
    float* out = (float*)d_out;

    init_kernel<<<1024, 256>>>(x, bkg_w, param_k, v0);

    histA_kernel<<<1024, 256>>>(rec_src);
    scanA_kernel<<<SC_NBLK, 256>>>();
    scanB_kernel<<<1, 64>>>();
    scanC_kernel<<<SC_NBLK, 256>>>();
    partition_kernel<<<(E_RECN + 255) / 256, 256>>>(rec_src, rec_tgt, w_rec);

    s0_kernel<<<(IN_QUADS + 255) / 256, 256>>>(in_src, in_tgt, w_in);

    int h = 0;
    for (int t = 0; t < TT; t++) {
        int h_read  = h;
        int h_write = (h + DD - 1) % DD;
        fused_kernel<<<F_GRID, 256>>>(decay, cf, v_th, e_l, v_reset, t_ref,
                                      asc_amps, param_g, syn_decay, psc_initial,
                                      (const float4*)bkg_w,
                                      in_src, in_tgt, w_in,
                                      out, t, h_read, h_write);
        h = h_write;
    }
}